// round 1
// baseline (speedup 1.0000x reference)
#include <cuda_runtime.h>
#include <math.h>

#define B_    8
#define SEQ   1024
#define DIM_  768
#define NH    12
#define HD_   64
#define QKVD  2304
#define SCALE_ 0.125f
#define EPS_   1e-6f

// Scratch (no allocations allowed): qkv = 75.5MB, att = 25.2MB
__device__ float g_qkv[(size_t)B_ * SEQ * QKVD];
__device__ float g_att[(size_t)B_ * SEQ * DIM_];

// ---------------------------------------------------------------------------
// SGEMM (NT): C[M,N] = A[M,K] @ W[N,K]^T (+ bias). 128x128x16 tiles, 8x8 micro.
// Split fragment mapping (tr*4 and 64+tr*4) keeps LDS.128 reads conflict-free.
// ---------------------------------------------------------------------------
__global__ __launch_bounds__(256) void sgemm_nt(
    const float* __restrict__ A, const float* __restrict__ W,
    const float* __restrict__ bias, float* __restrict__ C,
    int M, int N, int K)
{
    __shared__ float As[16][132];
    __shared__ float Ws[16][132];
    const int tid = threadIdx.x;
    const int tr = tid >> 4;          // 0..15
    const int tc = tid & 15;          // 0..15
    const int bm = blockIdx.y * 128;
    const int bn = blockIdx.x * 128;
    const int lr = tid >> 2;          // 0..63
    const int lc = (tid & 3) << 2;    // 0,4,8,12

    float acc[8][8];
#pragma unroll
    for (int i = 0; i < 8; i++)
#pragma unroll
        for (int j = 0; j < 8; j++) acc[i][j] = 0.f;

    const float* Ap = A + (size_t)(bm + lr) * K + lc;
    const float* Wp = W + (size_t)(bn + lr) * K + lc;

    for (int k0 = 0; k0 < K; k0 += 16) {
#pragma unroll
        for (int s = 0; s < 2; s++) {
            float4 av = *(const float4*)(Ap + (size_t)(s * 64) * K + k0);
            As[lc+0][lr + s*64] = av.x;
            As[lc+1][lr + s*64] = av.y;
            As[lc+2][lr + s*64] = av.z;
            As[lc+3][lr + s*64] = av.w;
            float4 wv = *(const float4*)(Wp + (size_t)(s * 64) * K + k0);
            Ws[lc+0][lr + s*64] = wv.x;
            Ws[lc+1][lr + s*64] = wv.y;
            Ws[lc+2][lr + s*64] = wv.z;
            Ws[lc+3][lr + s*64] = wv.w;
        }
        __syncthreads();
#pragma unroll
        for (int k = 0; k < 16; k++) {
            float a[8], b[8];
            *(float4*)(a)     = *(const float4*)&As[k][tr*4];
            *(float4*)(a + 4) = *(const float4*)&As[k][64 + tr*4];
            *(float4*)(b)     = *(const float4*)&Ws[k][tc*4];
            *(float4*)(b + 4) = *(const float4*)&Ws[k][64 + tc*4];
#pragma unroll
            for (int i = 0; i < 8; i++)
#pragma unroll
                for (int j = 0; j < 8; j++)
                    acc[i][j] = fmaf(a[i], b[j], acc[i][j]);
        }
        __syncthreads();
    }

    float bb[8];
#pragma unroll
    for (int j = 0; j < 8; j++)
        bb[j] = bias ? bias[bn + (j >> 2) * 64 + tc*4 + (j & 3)] : 0.f;

#pragma unroll
    for (int i = 0; i < 8; i++) {
        int row = bm + (i >> 2) * 64 + tr*4 + (i & 3);
        float4 v0 = make_float4(acc[i][0]+bb[0], acc[i][1]+bb[1],
                                acc[i][2]+bb[2], acc[i][3]+bb[3]);
        float4 v1 = make_float4(acc[i][4]+bb[4], acc[i][5]+bb[5],
                                acc[i][6]+bb[6], acc[i][7]+bb[7]);
        *(float4*)&C[(size_t)row * N + bn + tc*4]      = v0;
        *(float4*)&C[(size_t)row * N + bn + 64 + tc*4] = v1;
    }
}

// ---------------------------------------------------------------------------
// Fused attention: flash-style streaming softmax with policy weighting.
// One block = (query tile of 64, head, batch). 64x64 KV tiles, 4x4 micro.
// a_ij = (e_ij * p_j + EPS/N) / (sum_j e_ij*p_j + EPS), p_jj = 1.
// out_i = (acc_i + (EPS/N)*vsum) / (l_i + EPS).
// ---------------------------------------------------------------------------
__global__ __launch_bounds__(256) void attn_kernel(const float* __restrict__ policy)
{
    extern __shared__ float sm[];
    float (*Qs)[68] = (float(*)[68])sm;              // [d][row], pre-scaled
    float (*Ks)[68] = (float(*)[68])(sm + 64*68);    // [d][col]; reused as Ps[j][row]
    float (*Vs)[68] = (float(*)[68])(sm + 2*64*68);  // [j][d]
    float* pol = sm + 3*64*68;                       // [64]

    const int it = blockIdx.x;
    const int h  = blockIdx.y;
    const int b  = blockIdx.z;
    const int tid = threadIdx.x;
    const int tr = tid >> 4, tc = tid & 15;
    const int lr  = tid >> 2;          // 0..63
    const int ld0 = (tid & 3) << 4;    // 0,16,32,48

    // Load Q tile (transposed, scaled)
    {
        const float* qb = g_qkv + (size_t)(b*SEQ + it*64 + lr) * QKVD + h*HD_;
#pragma unroll
        for (int u = 0; u < 4; u++) {
            int d = ld0 + u*4;
            float4 v = *(const float4*)(qb + d);
            Qs[d+0][lr] = v.x * SCALE_;
            Qs[d+1][lr] = v.y * SCALE_;
            Qs[d+2][lr] = v.z * SCALE_;
            Qs[d+3][lr] = v.w * SCALE_;
        }
    }

    float m_run[4], lsum[4], acc[4][4], vsum[4];
#pragma unroll
    for (int i = 0; i < 4; i++) {
        m_run[i] = -3.0e38f; lsum[i] = 0.f; vsum[i] = 0.f;
#pragma unroll
        for (int c = 0; c < 4; c++) acc[i][c] = 0.f;
    }

    const int grow = it*64 + tr*4;

    for (int jt = 0; jt < 16; jt++) {
        __syncthreads();  // previous tile's PV reads done before overwrite
        const float* kb = g_qkv + (size_t)(b*SEQ + jt*64 + lr) * QKVD + DIM_ + h*HD_;
#pragma unroll
        for (int u = 0; u < 4; u++) {
            int d = ld0 + u*4;
            float4 kv = *(const float4*)(kb + d);
            Ks[d+0][lr] = kv.x; Ks[d+1][lr] = kv.y;
            Ks[d+2][lr] = kv.z; Ks[d+3][lr] = kv.w;
            float4 vv = *(const float4*)(kb + DIM_ + d);
            *(float4*)&Vs[lr][d] = vv;
        }
        if (tid < 64) pol[tid] = policy[(size_t)b*SEQ + jt*64 + tid];
        __syncthreads();

        // S = (Q*scale) @ K^T
        float s[4][4];
#pragma unroll
        for (int i = 0; i < 4; i++)
#pragma unroll
            for (int c = 0; c < 4; c++) s[i][c] = 0.f;

#pragma unroll 16
        for (int d = 0; d < 64; d++) {
            float4 qa = *(const float4*)&Qs[d][tr*4];
            float4 ka = *(const float4*)&Ks[d][tc*4];
            float qv[4] = {qa.x, qa.y, qa.z, qa.w};
            float kv[4] = {ka.x, ka.y, ka.z, ka.w};
#pragma unroll
            for (int i = 0; i < 4; i++)
#pragma unroll
                for (int c = 0; c < 4; c++)
                    s[i][c] = fmaf(qv[i], kv[c], s[i][c]);
        }

        // Online softmax with policy weighting
#pragma unroll
        for (int i = 0; i < 4; i++) {
            float mt = fmaxf(fmaxf(s[i][0], s[i][1]), fmaxf(s[i][2], s[i][3]));
#pragma unroll
            for (int o = 8; o > 0; o >>= 1)
                mt = fmaxf(mt, __shfl_xor_sync(0xffffffffu, mt, o));
            float mnew = fmaxf(m_run[i], mt);
            float corr = __expf(m_run[i] - mnew);
            m_run[i] = mnew;
            float ps = 0.f;
            int gc = jt*64 + tc*4;
#pragma unroll
            for (int c = 0; c < 4; c++) {
                float pf = (gc + c == grow + i) ? 1.f : pol[tc*4 + c];
                float p = __expf(s[i][c] - mnew) * pf;
                s[i][c] = p;
                ps += p;
            }
#pragma unroll
            for (int o = 8; o > 0; o >>= 1)
                ps += __shfl_xor_sync(0xffffffffu, ps, o);
            lsum[i] = lsum[i] * corr + ps;
#pragma unroll
            for (int c = 0; c < 4; c++) acc[i][c] *= corr;
        }

        __syncthreads();  // all Ks reads done before aliasing as Ps
        float (*Ps)[68] = Ks;
#pragma unroll
        for (int i = 0; i < 4; i++)
#pragma unroll
            for (int c = 0; c < 4; c++)
                Ps[tc*4 + c][tr*4 + i] = s[i][c];
        __syncthreads();

        // acc += P @ V ; vsum += column sums of V (free inside the loop)
#pragma unroll 8
        for (int j = 0; j < 64; j++) {
            float4 pa = *(const float4*)&Ps[j][tr*4];
            float4 vb = *(const float4*)&Vs[j][tc*4];
            float pv[4] = {pa.x, pa.y, pa.z, pa.w};
            float vv[4] = {vb.x, vb.y, vb.z, vb.w};
#pragma unroll
            for (int i = 0; i < 4; i++)
#pragma unroll
                for (int c = 0; c < 4; c++)
                    acc[i][c] = fmaf(pv[i], vv[c], acc[i][c]);
            vsum[0] += vv[0]; vsum[1] += vv[1];
            vsum[2] += vv[2]; vsum[3] += vv[3];
        }
    }

    const float epsn = EPS_ / (float)SEQ;
#pragma unroll
    for (int i = 0; i < 4; i++) {
        float inv = 1.f / (lsum[i] + EPS_);
        int row = grow + i;
        float4 o;
        o.x = (acc[i][0] + epsn * vsum[0]) * inv;
        o.y = (acc[i][1] + epsn * vsum[1]) * inv;
        o.z = (acc[i][2] + epsn * vsum[2]) * inv;
        o.w = (acc[i][3] + epsn * vsum[3]) * inv;
        *(float4*)&g_att[(size_t)(b*SEQ + row) * DIM_ + h*HD_ + tc*4] = o;
    }
}

// ---------------------------------------------------------------------------
extern "C" void kernel_launch(void* const* d_in, const int* in_sizes, int n_in,
                              void* d_out, int out_size)
{
    const float* x      = (const float*)d_in[0];
    const float* policy = (const float*)d_in[1];
    const float* qkv_w  = (const float*)d_in[2];
    const float* proj_w = (const float*)d_in[3];
    const float* proj_b = (const float*)d_in[4];
    float* out = (float*)d_out;

    float* qkv_buf; float* att_buf;
    cudaGetSymbolAddress((void**)&qkv_buf, g_qkv);
    cudaGetSymbolAddress((void**)&att_buf, g_att);

    const int attn_smem = (3 * 64 * 68 + 64) * 4;  // 52480 B
    cudaFuncSetAttribute(attn_kernel,
                         cudaFuncAttributeMaxDynamicSharedMemorySize, attn_smem);

    dim3 blk(256);
    // 1) QKV = x @ qkv_w^T
    sgemm_nt<<<dim3(QKVD/128, (B_*SEQ)/128), blk>>>(
        x, qkv_w, nullptr, qkv_buf, B_*SEQ, QKVD, DIM_);
    // 2) Fused attention (policy softmax) -> g_att in [B,N,H*HD] layout
    attn_kernel<<<dim3(SEQ/64, NH, B_), blk, attn_smem>>>(policy);
    // 3) out = att @ proj_w^T + proj_b
    sgemm_nt<<<dim3(DIM_/128, (B_*SEQ)/128), blk>>>(
        att_buf, proj_w, proj_b, out, B_*SEQ, DIM_, DIM_);
}

// round 2
// speedup vs baseline: 2.8530x; 2.8530x over previous
#include <cuda_runtime.h>
#include <math.h>
#include <stdint.h>

#define B_    8
#define SEQ   1024
#define DIM_  768
#define NH    12
#define HD_   64
#define QKVD  2304
#define SCALE_ 0.125f
#define EPS_   1e-6f
#define EPSN_  9.765625e-10f   /* EPS_/1024 */
#define LOG2E_ 1.4426950408889634f

// Scratch (no allocations allowed)
__device__ float g_qkv[(size_t)B_ * SEQ * QKVD];
__device__ float g_att[(size_t)B_ * SEQ * DIM_];

// f32 -> tf32 with round-to-nearest (unbiased; HW mma truncates otherwise)
__device__ __forceinline__ float f2tff(float x) {
    unsigned u;
    asm("cvt.rna.tf32.f32 %0, %1;" : "=r"(u) : "f"(x));
    return __uint_as_float(u);
}
__device__ __forceinline__ float ex2f(float x) {
    float y;
    asm("ex2.approx.f32 %0, %1;" : "=f"(y) : "f"(x));
    return y;
}
// m16n8k8 row.col tf32 MMA, fp32 accumulate (D += A*B)
__device__ __forceinline__ void mma8(float d[4], const float a[4], const float b[2]) {
    asm volatile(
        "mma.sync.aligned.m16n8k8.row.col.f32.tf32.tf32.f32 "
        "{%0,%1,%2,%3}, {%4,%5,%6,%7}, {%8,%9}, {%0,%1,%2,%3};"
        : "+f"(d[0]), "+f"(d[1]), "+f"(d[2]), "+f"(d[3])
        : "r"(__float_as_uint(a[0])), "r"(__float_as_uint(a[1])),
          "r"(__float_as_uint(a[2])), "r"(__float_as_uint(a[3])),
          "r"(__float_as_uint(b[0])), "r"(__float_as_uint(b[1])));
}

// ---------------------------------------------------------------------------
// tf32 GEMM (NT): C[M,N] = A[M,K] @ W[N,K]^T (+bias). 128x128x32 tiles.
// 8 warps in 2x4 grid, warp tile 64x32 (4x4 m16n8 tiles).
// Smem padded to stride 36 -> fragment LDS addresses (4g+q) mod 32: conflict-free.
// ---------------------------------------------------------------------------
__global__ __launch_bounds__(256) void gemm_tf32(
    const float* __restrict__ A, const float* __restrict__ W,
    const float* __restrict__ bias, float* __restrict__ C,
    int M, int N, int K)
{
    __shared__ float As[128][36];
    __shared__ float Ws[128][36];
    const int tid = threadIdx.x;
    const int lane = tid & 31, wid = tid >> 5;
    const int wm = (wid >> 2) * 64, wn = (wid & 3) * 32;
    const int g = lane >> 2, q = lane & 3;
    const int bm = blockIdx.y * 128, bn = blockIdx.x * 128;
    const int lr = tid >> 3, lc = (tid & 7) << 2;

    float acc[4][4][4];
#pragma unroll
    for (int i = 0; i < 4; i++)
#pragma unroll
        for (int j = 0; j < 4; j++)
#pragma unroll
            for (int r = 0; r < 4; r++) acc[i][j][r] = 0.f;

    const float* Ap = A + (size_t)(bm + lr) * K + lc;
    const float* Wp = W + (size_t)(bn + lr) * K + lc;

    float4 ra[4], rw[4];
#pragma unroll
    for (int s = 0; s < 4; s++) {
        ra[s] = *(const float4*)(Ap + (size_t)s * 32 * K);
        rw[s] = *(const float4*)(Wp + (size_t)s * 32 * K);
    }

    for (int k0 = 0; k0 < K; k0 += 32) {
#pragma unroll
        for (int s = 0; s < 4; s++) {
            As[lr + s*32][lc+0] = f2tff(ra[s].x); As[lr + s*32][lc+1] = f2tff(ra[s].y);
            As[lr + s*32][lc+2] = f2tff(ra[s].z); As[lr + s*32][lc+3] = f2tff(ra[s].w);
            Ws[lr + s*32][lc+0] = f2tff(rw[s].x); Ws[lr + s*32][lc+1] = f2tff(rw[s].y);
            Ws[lr + s*32][lc+2] = f2tff(rw[s].z); Ws[lr + s*32][lc+3] = f2tff(rw[s].w);
        }
        __syncthreads();
        if (k0 + 32 < K) {
#pragma unroll
            for (int s = 0; s < 4; s++) {
                ra[s] = *(const float4*)(Ap + (size_t)s * 32 * K + k0 + 32);
                rw[s] = *(const float4*)(Wp + (size_t)s * 32 * K + k0 + 32);
            }
        }
#pragma unroll
        for (int kk = 0; kk < 32; kk += 8) {
            float af[4][4], bf[4][2];
#pragma unroll
            for (int mt = 0; mt < 4; mt++) {
                int r = wm + mt*16 + g;
                af[mt][0] = As[r][kk+q];     af[mt][1] = As[r+8][kk+q];
                af[mt][2] = As[r][kk+q+4];   af[mt][3] = As[r+8][kk+q+4];
            }
#pragma unroll
            for (int nt = 0; nt < 4; nt++) {
                int n = wn + nt*8 + g;
                bf[nt][0] = Ws[n][kk+q];     bf[nt][1] = Ws[n][kk+q+4];
            }
#pragma unroll
            for (int mt = 0; mt < 4; mt++)
#pragma unroll
                for (int nt = 0; nt < 4; nt++)
                    mma8(acc[mt][nt], af[mt], bf[nt]);
        }
        __syncthreads();
    }

#pragma unroll
    for (int mt = 0; mt < 4; mt++) {
        int r0 = bm + wm + mt*16 + g;
#pragma unroll
        for (int nt = 0; nt < 4; nt++) {
            int c = bn + wn + nt*8 + 2*q;
            float b0 = bias ? bias[c]   : 0.f;
            float b1 = bias ? bias[c+1] : 0.f;
            *(float2*)&C[(size_t)r0 * N + c] =
                make_float2(acc[mt][nt][0] + b0, acc[mt][nt][1] + b1);
            *(float2*)&C[(size_t)(r0+8) * N + c] =
                make_float2(acc[mt][nt][2] + b0, acc[mt][nt][3] + b1);
        }
    }
}

// ---------------------------------------------------------------------------
// Fused attention, tf32 tensor-core flash style.
// Block = (128 q-rows, head, batch). KV tiles of 64.
// S phase: warps 2x4 (warp 64x16); PV phase: warps 4x2 (warp 32x32).
// P' = exp(s - m)*policy + EPS/N  ->  out = (P'·V) / rowsum(P')  (exact match
// to reference since sum_j(p+EPS/N) = sum_j p + EPS).
// ---------------------------------------------------------------------------
__global__ __launch_bounds__(256) void attn_tf32(const float* __restrict__ policy)
{
    extern __shared__ float sm[];
    float (*Qs)[68]  = (float(*)[68])(sm);                          // 128x68
    float (*Ks)[68]  = (float(*)[68])(sm + 128*68);                 // 64x68
    float (*Ps)[68]  = (float(*)[68])(sm + 128*68 + 64*68);         // 128x68
    float (*Vts)[68] = (float(*)[68])(sm + 2*128*68 + 64*68);       // 64x68 (V^T)
    float* pol    = sm + 2*128*68 + 2*64*68;   // 64
    float* mstate = pol + 64;                  // 128
    float* corr_s = mstate + 128;              // 128
    float* lstate = corr_s + 128;              // 128
    float (*red)[4] = (float(*)[4])(lstate + 128);  // 128x4

    const int it = blockIdx.x, h = blockIdx.y, b = blockIdx.z;
    const int tid = threadIdx.x, lane = tid & 31, wid = tid >> 5;
    const int g = lane >> 2, q = lane & 3;
    const int wmS = (wid >> 2) * 64, wnS = (wid & 3) * 16, wcS = wid & 3;
    const int wmP = (wid >> 1) * 32, wnP = (wid & 1) * 32;
    const int qrow0 = it * 128;

    // Load Q tile (scaled, tf32-rounded)
    {
        const size_t base = ((size_t)(b * SEQ) + qrow0) * QKVD + h * HD_;
#pragma unroll
        for (int p = 0; p < 8; p++) {
            int idx = tid + p * 256;
            int r = idx >> 4, c = (idx & 15) * 4;
            float4 v = *(const float4*)&g_qkv[base + (size_t)r * QKVD + c];
            Qs[r][c+0] = f2tff(v.x * SCALE_); Qs[r][c+1] = f2tff(v.y * SCALE_);
            Qs[r][c+2] = f2tff(v.z * SCALE_); Qs[r][c+3] = f2tff(v.w * SCALE_);
        }
    }
    if (tid < 128) { mstate[tid] = -INFINITY; lstate[tid] = 0.f; }

    float o_acc[2][4][4];
#pragma unroll
    for (int i = 0; i < 2; i++)
#pragma unroll
        for (int j = 0; j < 4; j++)
#pragma unroll
            for (int r = 0; r < 4; r++) o_acc[i][j][r] = 0.f;

    for (int jt = 0; jt < 16; jt++) {
        __syncthreads();  // prev PV done reading Ps/Vts; Q/init visible on jt=0
        {
            const size_t kbase = ((size_t)(b * SEQ) + jt * 64) * QKVD + DIM_ + h * HD_;
#pragma unroll
            for (int p = 0; p < 4; p++) {
                int idx = tid + p * 256;
                int r = idx >> 4, c = (idx & 15) * 4;
                float4 kv = *(const float4*)&g_qkv[kbase + (size_t)r * QKVD + c];
                Ks[r][c+0] = f2tff(kv.x); Ks[r][c+1] = f2tff(kv.y);
                Ks[r][c+2] = f2tff(kv.z); Ks[r][c+3] = f2tff(kv.w);
                float4 vv = *(const float4*)&g_qkv[kbase + DIM_ + (size_t)r * QKVD + c];
                Vts[c+0][r] = f2tff(vv.x); Vts[c+1][r] = f2tff(vv.y);
                Vts[c+2][r] = f2tff(vv.z); Vts[c+3][r] = f2tff(vv.w);
            }
            if (tid < 64) pol[tid] = policy[(size_t)b * SEQ + jt * 64 + tid];
        }
        __syncthreads();

        // ---- S = Q @ K^T (warp 64x16) ----
        float s_acc[4][2][4];
#pragma unroll
        for (int i = 0; i < 4; i++)
#pragma unroll
            for (int j = 0; j < 2; j++)
#pragma unroll
                for (int r = 0; r < 4; r++) s_acc[i][j][r] = 0.f;
#pragma unroll
        for (int kk = 0; kk < 64; kk += 8) {
            float af[4][4], bf[2][2];
#pragma unroll
            for (int mt = 0; mt < 4; mt++) {
                int r = wmS + mt*16 + g;
                af[mt][0] = Qs[r][kk+q];     af[mt][1] = Qs[r+8][kk+q];
                af[mt][2] = Qs[r][kk+q+4];   af[mt][3] = Qs[r+8][kk+q+4];
            }
#pragma unroll
            for (int nt = 0; nt < 2; nt++) {
                int n = wnS + nt*8 + g;
                bf[nt][0] = Ks[n][kk+q];     bf[nt][1] = Ks[n][kk+q+4];
            }
#pragma unroll
            for (int mt = 0; mt < 4; mt++)
#pragma unroll
                for (int nt = 0; nt < 2; nt++)
                    mma8(s_acc[mt][nt], af[mt], bf[nt]);
        }

        // ---- row-max partials (quad shuffle then cross-warp via smem) ----
#pragma unroll
        for (int mt = 0; mt < 4; mt++) {
            int r0 = wmS + mt*16 + g;
            float m0 = fmaxf(fmaxf(s_acc[mt][0][0], s_acc[mt][0][1]),
                             fmaxf(s_acc[mt][1][0], s_acc[mt][1][1]));
            float m1 = fmaxf(fmaxf(s_acc[mt][0][2], s_acc[mt][0][3]),
                             fmaxf(s_acc[mt][1][2], s_acc[mt][1][3]));
            m0 = fmaxf(m0, __shfl_xor_sync(0xffffffffu, m0, 1));
            m0 = fmaxf(m0, __shfl_xor_sync(0xffffffffu, m0, 2));
            m1 = fmaxf(m1, __shfl_xor_sync(0xffffffffu, m1, 1));
            m1 = fmaxf(m1, __shfl_xor_sync(0xffffffffu, m1, 2));
            if (q == 0) { red[r0][wcS] = m0; red[r0+8][wcS] = m1; }
        }
        __syncthreads();
        if (tid < 128) {
            float mt4 = fmaxf(fmaxf(red[tid][0], red[tid][1]),
                              fmaxf(red[tid][2], red[tid][3]));
            float mo = mstate[tid];
            float mn = fmaxf(mo, mt4);
            corr_s[tid] = ex2f((mo - mn) * LOG2E_);
            mstate[tid] = mn;
        }
        __syncthreads();

        // ---- p = exp(s-m)*policy + EPS/N; store to Ps; row sums ----
#pragma unroll
        for (int mt = 0; mt < 4; mt++) {
            int r0 = wmS + mt*16 + g, r1 = r0 + 8;
            float m0 = mstate[r0], m1 = mstate[r1];
            float sum0 = 0.f, sum1 = 0.f;
#pragma unroll
            for (int nt = 0; nt < 2; nt++) {
                int cl = wnS + nt*8 + 2*q;
                int jg = jt*64 + cl;
                float pf0 = pol[cl], pf1 = pol[cl+1];
                float p00 = ex2f((s_acc[mt][nt][0] - m0) * LOG2E_)
                            * ((jg   == qrow0 + r0) ? 1.f : pf0) + EPSN_;
                float p01 = ex2f((s_acc[mt][nt][1] - m0) * LOG2E_)
                            * ((jg+1 == qrow0 + r0) ? 1.f : pf1) + EPSN_;
                float p10 = ex2f((s_acc[mt][nt][2] - m1) * LOG2E_)
                            * ((jg   == qrow0 + r1) ? 1.f : pf0) + EPSN_;
                float p11 = ex2f((s_acc[mt][nt][3] - m1) * LOG2E_)
                            * ((jg+1 == qrow0 + r1) ? 1.f : pf1) + EPSN_;
                sum0 += p00 + p01; sum1 += p10 + p11;
                *(float2*)&Ps[r0][cl] = make_float2(f2tff(p00), f2tff(p01));
                *(float2*)&Ps[r1][cl] = make_float2(f2tff(p10), f2tff(p11));
            }
            sum0 += __shfl_xor_sync(0xffffffffu, sum0, 1);
            sum0 += __shfl_xor_sync(0xffffffffu, sum0, 2);
            sum1 += __shfl_xor_sync(0xffffffffu, sum1, 1);
            sum1 += __shfl_xor_sync(0xffffffffu, sum1, 2);
            if (q == 0) { red[r0][wcS] = sum0; red[r1][wcS] = sum1; }
        }
        __syncthreads();
        if (tid < 128) {
            float s4 = red[tid][0] + red[tid][1] + red[tid][2] + red[tid][3];
            lstate[tid] = lstate[tid] * corr_s[tid] + s4;
        }

        // ---- PV: o = o*corr + P' @ V (warp 32x32) ----
        {
            float c0[2], c1[2];
#pragma unroll
            for (int mt = 0; mt < 2; mt++) {
                int r = wmP + mt*16 + g;
                c0[mt] = corr_s[r]; c1[mt] = corr_s[r+8];
            }
#pragma unroll
            for (int mt = 0; mt < 2; mt++)
#pragma unroll
                for (int nt = 0; nt < 4; nt++) {
                    o_acc[mt][nt][0] *= c0[mt]; o_acc[mt][nt][1] *= c0[mt];
                    o_acc[mt][nt][2] *= c1[mt]; o_acc[mt][nt][3] *= c1[mt];
                }
#pragma unroll
            for (int kk = 0; kk < 64; kk += 8) {
                float af[2][4], bf[4][2];
#pragma unroll
                for (int mt = 0; mt < 2; mt++) {
                    int r = wmP + mt*16 + g;
                    af[mt][0] = Ps[r][kk+q];     af[mt][1] = Ps[r+8][kk+q];
                    af[mt][2] = Ps[r][kk+q+4];   af[mt][3] = Ps[r+8][kk+q+4];
                }
#pragma unroll
                for (int nt = 0; nt < 4; nt++) {
                    int n = wnP + nt*8 + g;
                    bf[nt][0] = Vts[n][kk+q];    bf[nt][1] = Vts[n][kk+q+4];
                }
#pragma unroll
                for (int mt = 0; mt < 2; mt++)
#pragma unroll
                    for (int nt = 0; nt < 4; nt++)
                        mma8(o_acc[mt][nt], af[mt], bf[nt]);
            }
        }
    }

    __syncthreads();  // lstate final values visible
#pragma unroll
    for (int mt = 0; mt < 2; mt++) {
        int r = wmP + mt*16 + g;
        float inv0 = 1.f / lstate[r];
        float inv1 = 1.f / lstate[r+8];
        size_t ro0 = ((size_t)(b * SEQ) + qrow0 + r) * DIM_ + h * HD_;
        size_t ro1 = ((size_t)(b * SEQ) + qrow0 + r + 8) * DIM_ + h * HD_;
#pragma unroll
        for (int nt = 0; nt < 4; nt++) {
            int c = wnP + nt*8 + 2*q;
            *(float2*)&g_att[ro0 + c] =
                make_float2(o_acc[mt][nt][0] * inv0, o_acc[mt][nt][1] * inv0);
            *(float2*)&g_att[ro1 + c] =
                make_float2(o_acc[mt][nt][2] * inv1, o_acc[mt][nt][3] * inv1);
        }
    }
}

// ---------------------------------------------------------------------------
extern "C" void kernel_launch(void* const* d_in, const int* in_sizes, int n_in,
                              void* d_out, int out_size)
{
    const float* x      = (const float*)d_in[0];
    const float* policy = (const float*)d_in[1];
    const float* qkv_w  = (const float*)d_in[2];
    const float* proj_w = (const float*)d_in[3];
    const float* proj_b = (const float*)d_in[4];
    float* out = (float*)d_out;

    float* qkv_buf; float* att_buf;
    cudaGetSymbolAddress((void**)&qkv_buf, g_qkv);
    cudaGetSymbolAddress((void**)&att_buf, g_att);

    const int attn_smem =
        (2*128*68 + 2*64*68 + 64 + 3*128 + 128*4) * (int)sizeof(float);
    cudaFuncSetAttribute(attn_tf32,
                         cudaFuncAttributeMaxDynamicSharedMemorySize, attn_smem);

    // 1) QKV = x @ qkv_w^T
    gemm_tf32<<<dim3(QKVD/128, (B_*SEQ)/128), 256>>>(
        x, qkv_w, nullptr, qkv_buf, B_*SEQ, QKVD, DIM_);
    // 2) Fused policy-softmax attention -> g_att [B*N, H*HD]
    attn_tf32<<<dim3(SEQ/128, NH, B_), 256, attn_smem>>>(policy);
    // 3) out = att @ proj_w^T + proj_b
    gemm_tf32<<<dim3(DIM_/128, (B_*SEQ)/128), 256>>>(
        att_buf, proj_w, proj_b, out, B_*SEQ, DIM_, DIM_);
}